// round 12
// baseline (speedup 1.0000x reference)
#include <cuda_runtime.h>
#include <cuda_bf16.h>
#include <math.h>

#define N 8192
#define EPS 1e-5f
#define FACT 2.0f
#define PD_EPS 1e-6f
#define CUTOFF 25.0f
#define DENSE_TH 50.0f   // rows with m < 50 handled by dense_kernel

#define RW 4
#define TPB 64
#define GRID (N / RW)    // 2048 CTAs; 14/SM -> single wave
#define GRID_D 592       // dense kernel CTAs (4/SM)
#define TPB_D 128

__device__ float4 g_p2[N];        // packed {x, y, z, -0.5*|p|^2}
__device__ float g_rowm[N];       // softmax max arg per row (exact)
__device__ float g_rowth[N];      // gate threshold in h-space (+inf for dense)
__device__ float g_pd[N];         // per-row pairwise distance
__device__ int g_dense_rows[N];   // compacted dense row indices
__device__ int g_dense_cnt;       // number of dense rows
__device__ int g_done;            // dense-kernel completion counter

// h = dot(p1, p2_j) - 0.5*|p2_j|^2  (argmax h == argmin d2; d2 = s1 - 2h)
__device__ __forceinline__ float hdot(float x, float y, float z, float4 p) {
    return fmaf(x, p.x, fmaf(y, p.y, fmaf(z, p.z, p.w)));
}

__global__ void prep_kernel(const float* __restrict__ pc2) {
    int j = blockIdx.x * blockDim.x + threadIdx.x;
    if (j == 0) { g_dense_cnt = 0; g_done = 0; }   // re-seed (graph-replay safe)
    if (j < N) {
        float x = pc2[j], y = pc2[N + j], z = pc2[2 * N + j];
        g_p2[j] = make_float4(x, y, z, -0.5f * fmaf(x, x, fmaf(y, y, z * z)));
    }
}

// ---- K1: exact per-row hmax -> m, hth; append dense rows to compact list ----
__global__ __launch_bounds__(TPB, 14)
void max_kernel(const float* __restrict__ pc1) {
    __shared__ float s_hm[2][RW];
    const int tid = threadIdx.x;
    const int lane = tid & 31;
    const int wrp = tid >> 5;
    const int row0 = blockIdx.x * RW;
    const float4* __restrict__ p2 = g_p2;

    float xs[RW], ys[RW], zs[RW], s1[RW];
#pragma unroll
    for (int r = 0; r < RW; r++) {
        int i = row0 + r;
        xs[r] = pc1[i];
        ys[r] = pc1[N + i];
        zs[r] = pc1[2 * N + i];
        s1[r] = fmaf(xs[r], xs[r], fmaf(ys[r], ys[r], zs[r] * zs[r]));
    }

    float hm[RW];
#pragma unroll
    for (int r = 0; r < RW; r++) hm[r] = -3.4e38f;

    for (int j = tid; j < N; j += 4 * TPB) {   // unroll x4, MLP 4
        float4 pa = p2[j];
        float4 pb = p2[j + TPB];
        float4 pc = p2[j + 2 * TPB];
        float4 pd = p2[j + 3 * TPB];
#pragma unroll
        for (int r = 0; r < RW; r++) {
            float a = fmaxf(hdot(xs[r], ys[r], zs[r], pa),
                            hdot(xs[r], ys[r], zs[r], pb));
            float b = fmaxf(hdot(xs[r], ys[r], zs[r], pc),
                            hdot(xs[r], ys[r], zs[r], pd));
            hm[r] = fmaxf(hm[r], fmaxf(a, b));
        }
    }
#pragma unroll
    for (int r = 0; r < RW; r++) {
#pragma unroll
        for (int ofs = 16; ofs > 0; ofs >>= 1)
            hm[r] = fmaxf(hm[r], __shfl_xor_sync(0xFFFFFFFFu, hm[r], ofs));
    }
    if (lane == 0) {
#pragma unroll
        for (int r = 0; r < RW; r++) s_hm[wrp][r] = hm[r];
    }
    __syncthreads();

    if (tid < RW) {
        int r = tid;
        float h = fmaxf(s_hm[0][r], s_hm[1][r]);           // exact fp32 row max
        float mind2 = fmaf(-2.0f, h, s1[r]);
        float mm = FACT / fmaxf(mind2, EPS);
        float hth;
        if (mm < DENSE_TH) {
            hth = __int_as_float(0x7f800000);               // +inf: gate off in K2
            int e = atomicAdd(&g_dense_cnt, 1);
            g_dense_rows[e] = row0 + r;
        } else {
            float t = 0.5f * (s1[r] - FACT / (mm - CUTOFF));
            hth = fminf(t, h);   // clamp: argmax qualifies bitwise in K2
        }
        g_rowm[row0 + r] = mm;
        g_rowth[row0 + r] = hth;
    }
}

// ---- K2: gated softmax accumulation for sparse rows (uniform cost) ----
__global__ __launch_bounds__(TPB, 14)
void acc_kernel(const float* __restrict__ pc1, float* __restrict__ out) {
    __shared__ float s_acc[2][RW][4];
    const int tid = threadIdx.x;
    const int lane = tid & 31;
    const int wrp = tid >> 5;
    const int row0 = blockIdx.x * RW;
    const float4* __restrict__ p2 = g_p2;

    float xs[RW], ys[RW], zs[RW], s1[RW], m[RW], hth[RW];
#pragma unroll
    for (int r = 0; r < RW; r++) {
        int i = row0 + r;
        xs[r] = pc1[i];
        ys[r] = pc1[N + i];
        zs[r] = pc1[2 * N + i];
        s1[r] = fmaf(xs[r], xs[r], fmaf(ys[r], ys[r], zs[r] * zs[r]));
        m[r] = g_rowm[i];
        hth[r] = g_rowth[i];
    }
    // Hoisted conservative gate threshold (min over rows; +inf rows drop out)
    float hthmin = fminf(fminf(hth[0], hth[1]), fminf(hth[2], hth[3]));

    float sw[RW], ax[RW], ay[RW], az[RW];
#pragma unroll
    for (int r = 0; r < RW; r++) { sw[r] = 0.f; ax[r] = 0.f; ay[r] = 0.f; az[r] = 0.f; }

    for (int j = tid; j < N; j += 2 * TPB) {   // unroll x2, regs stay < 73
        float4 pa = p2[j];
        float4 pb = p2[j + TPB];
        float ha[RW], hb[RW];
        float g = -3.4e38f;
#pragma unroll
        for (int r = 0; r < RW; r++) {
            ha[r] = hdot(xs[r], ys[r], zs[r], pa);   // identical chain to K1
            hb[r] = hdot(xs[r], ys[r], zs[r], pb);
            g = fmaxf(g, fmaxf(ha[r], hb[r]));
        }
        if (g >= hthmin) {   // rare: tight qualifier ball for sparse rows
#pragma unroll
            for (int r = 0; r < RW; r++) {
                if (ha[r] >= hth[r]) {
                    float d2 = fmaf(-2.0f, ha[r], s1[r]);
                    float w = __expf(FACT / fmaxf(d2, EPS) - m[r]);
                    sw[r] += w;
                    ax[r] = fmaf(w, pa.x, ax[r]);
                    ay[r] = fmaf(w, pa.y, ay[r]);
                    az[r] = fmaf(w, pa.z, az[r]);
                }
                if (hb[r] >= hth[r]) {
                    float d2 = fmaf(-2.0f, hb[r], s1[r]);
                    float w = __expf(FACT / fmaxf(d2, EPS) - m[r]);
                    sw[r] += w;
                    ax[r] = fmaf(w, pb.x, ax[r]);
                    ay[r] = fmaf(w, pb.y, ay[r]);
                    az[r] = fmaf(w, pb.z, az[r]);
                }
            }
        }
    }

#pragma unroll
    for (int r = 0; r < RW; r++) {
#pragma unroll
        for (int ofs = 16; ofs > 0; ofs >>= 1) {
            sw[r] += __shfl_xor_sync(0xFFFFFFFFu, sw[r], ofs);
            ax[r] += __shfl_xor_sync(0xFFFFFFFFu, ax[r], ofs);
            ay[r] += __shfl_xor_sync(0xFFFFFFFFu, ay[r], ofs);
            az[r] += __shfl_xor_sync(0xFFFFFFFFu, az[r], ofs);
        }
    }
    if (lane == 0) {
#pragma unroll
        for (int r = 0; r < RW; r++) {
            s_acc[wrp][r][0] = sw[r];
            s_acc[wrp][r][1] = ax[r];
            s_acc[wrp][r][2] = ay[r];
            s_acc[wrp][r][3] = az[r];
        }
    }
    __syncthreads();

    if (tid < RW) {
        int r = tid;
        if (m[r] >= DENSE_TH) {             // dense rows owned by dense_kernel
            int i = row0 + r;
            float swt = s_acc[0][r][0] + s_acc[1][r][0];
            float axt = s_acc[0][r][1] + s_acc[1][r][1];
            float ayt = s_acc[0][r][2] + s_acc[1][r][2];
            float azt = s_acc[0][r][3] + s_acc[1][r][3];
            float inv = 1.0f / swt;
            float px = axt * inv, py = ayt * inv, pz = azt * inv;
            out[i] = px;
            out[N + i] = py;
            out[2 * N + i] = pz;
            float dx = xs[r] - px + PD_EPS;
            float dy = ys[r] - py + PD_EPS;
            float dz = zs[r] - pz + PD_EPS;
            g_pd[i] = sqrtf(fmaf(dx, dx, fmaf(dy, dy, dz * dz)));
        }
    }
}

// ---- Dense rows via compact list; last CTA computes the mean ----
__global__ __launch_bounds__(TPB_D)
void dense_kernel(const float* __restrict__ pc1, float* __restrict__ out,
                  int out_size) {
    __shared__ float s_red[4][4];
    __shared__ float s_mean[4];
    __shared__ int s_last;

    const int tid = threadIdx.x;
    const int lane = tid & 31;
    const int wrp = tid >> 5;
    const int cnt = g_dense_cnt;             // written by max_kernel
    const float4* __restrict__ p2 = g_p2;

    for (int e = blockIdx.x; e < cnt; e += GRID_D) {
        const int row = g_dense_rows[e];
        const float m = g_rowm[row];
        float x1 = pc1[row], y1 = pc1[N + row], z1 = pc1[2 * N + row];
        float s1 = fmaf(x1, x1, fmaf(y1, y1, z1 * z1));

        float sw = 0.f, ax = 0.f, ay = 0.f, az = 0.f;
        for (int j = tid; j < N; j += 4 * TPB_D) {   // unroll x4, MLP 4
            float4 ps[4] = {p2[j], p2[j + TPB_D], p2[j + 2 * TPB_D], p2[j + 3 * TPB_D]};
#pragma unroll
            for (int q = 0; q < 4; q++) {
                float h = hdot(x1, y1, z1, ps[q]);
                float d2 = fmaf(-2.0f, h, s1);
                float w = __expf(FACT / fmaxf(d2, EPS) - m);   // m exact: no overflow
                sw += w;
                ax = fmaf(w, ps[q].x, ax);
                ay = fmaf(w, ps[q].y, ay);
                az = fmaf(w, ps[q].z, az);
            }
        }
#pragma unroll
        for (int ofs = 16; ofs > 0; ofs >>= 1) {
            sw += __shfl_xor_sync(0xFFFFFFFFu, sw, ofs);
            ax += __shfl_xor_sync(0xFFFFFFFFu, ax, ofs);
            ay += __shfl_xor_sync(0xFFFFFFFFu, ay, ofs);
            az += __shfl_xor_sync(0xFFFFFFFFu, az, ofs);
        }
        if (lane == 0) {
            s_red[wrp][0] = sw;
            s_red[wrp][1] = ax;
            s_red[wrp][2] = ay;
            s_red[wrp][3] = az;
        }
        __syncthreads();
        if (tid == 0) {
            float swt = 0.f, axt = 0.f, ayt = 0.f, azt = 0.f;
#pragma unroll
            for (int w4 = 0; w4 < 4; w4++) {   // fixed order: deterministic
                swt += s_red[w4][0];
                axt += s_red[w4][1];
                ayt += s_red[w4][2];
                azt += s_red[w4][3];
            }
            float inv = 1.0f / swt;
            float px = axt * inv, py = ayt * inv, pz = azt * inv;
            out[row] = px;
            out[N + row] = py;
            out[2 * N + row] = pz;
            float dx = x1 - px + PD_EPS;
            float dy = y1 - py + PD_EPS;
            float dz = z1 - pz + PD_EPS;
            g_pd[row] = sqrtf(fmaf(dx, dx, fmaf(dy, dy, dz * dz)));
        }
        __syncthreads();
    }

    // Completion handshake (ALL CTAs, incl. ones with no list entries)
    __threadfence();
    if (tid == 0) s_last = (atomicAdd(&g_done, 1) == GRID_D - 1);
    __syncthreads();
    if (s_last) {
        __threadfence();   // acquire: order g_pd reads after the counter
        float acc = 0.f;
        for (int i = tid; i < N; i += TPB_D) acc += __ldcg(&g_pd[i]);
#pragma unroll
        for (int ofs = 16; ofs > 0; ofs >>= 1)
            acc += __shfl_xor_sync(0xFFFFFFFFu, acc, ofs);
        if (lane == 0) s_mean[wrp] = acc;
        __syncthreads();
        if (tid == 0 && out_size > 3 * N)
            out[3 * N] = (s_mean[0] + s_mean[1] + s_mean[2] + s_mean[3]) * (1.0f / N);
    }
}

extern "C" void kernel_launch(void* const* d_in, const int* in_sizes, int n_in,
                              void* d_out, int out_size) {
    const float* pc1 = (const float*)d_in[0];
    const float* pc2 = (const float*)d_in[1];
    float* out = (float*)d_out;

    prep_kernel<<<(N + 255) / 256, 256>>>(pc2);
    max_kernel<<<GRID, TPB>>>(pc1);
    acc_kernel<<<GRID, TPB>>>(pc1, out);
    dense_kernel<<<GRID_D, TPB_D>>>(pc1, out, out_size);
}

// round 13
// speedup vs baseline: 1.5196x; 1.5196x over previous
#include <cuda_runtime.h>
#include <cuda_bf16.h>
#include <math.h>

#define N 8192
#define EPS 1e-5f
#define FACT 2.0f
#define PD_EPS 1e-6f
#define CUTOFF 25.0f
#define DENSE_TH 32.0f   // rows with m < 32 handled by dense_kernel

#define RW 4
#define TPB 64
#define GRID (N / RW)    // 2048 CTAs
#define GRID_D 1184      // dense kernel CTAs (8/SM at 256 thr)
#define TPB_D 256

__device__ float4 g_p2[N];        // packed {x, y, z, -0.5*|p|^2}
__device__ float g_rowm[N];       // softmax max arg per row (exact)
__device__ float g_pd[N];         // per-row pairwise distance
__device__ int g_dense_rows[N];   // compacted dense row indices
__device__ int g_dense_cnt;       // number of dense rows
__device__ int g_done;            // dense-kernel completion counter

// h = dot(p1, p2_j) - 0.5*|p2_j|^2  (argmax h == argmin d2; d2 = s1 - 2h)
__device__ __forceinline__ float hdot(float x, float y, float z, float4 p) {
    return fmaf(x, p.x, fmaf(y, p.y, fmaf(z, p.z, p.w)));
}

__global__ void prep_kernel(const float* __restrict__ pc2) {
    int j = blockIdx.x * blockDim.x + threadIdx.x;
    if (j == 0) { g_dense_cnt = 0; g_done = 0; }   // re-seed (graph-replay safe)
    if (j < N) {
        float x = pc2[j], y = pc2[N + j], z = pc2[2 * N + j];
        g_p2[j] = make_float4(x, y, z, -0.5f * fmaf(x, x, fmaf(y, y, z * z)));
    }
}

// ---- Fused: pass1 max -> classify -> pass2 gated acc (sparse rows only) ----
__global__ __launch_bounds__(TPB, 14)
void soft_knn_kernel(const float* __restrict__ pc1, float* __restrict__ out) {
    __shared__ float s_hm[2][RW];
    __shared__ float s_acc[2][RW][4];

    const int tid = threadIdx.x;
    const int lane = tid & 31;
    const int wrp = tid >> 5;
    const int row0 = blockIdx.x * RW;
    const float4* __restrict__ p2 = g_p2;

    float xs[RW], ys[RW], zs[RW], s1[RW];
#pragma unroll
    for (int r = 0; r < RW; r++) {
        int i = row0 + r;
        xs[r] = pc1[i];
        ys[r] = pc1[N + i];
        zs[r] = pc1[2 * N + i];
        s1[r] = fmaf(xs[r], xs[r], fmaf(ys[r], ys[r], zs[r] * zs[r]));
    }

    // ---- Pass 1: per-row hmax; 64 threads sweep j, unroll x4 ----
    float hm[RW];
#pragma unroll
    for (int r = 0; r < RW; r++) hm[r] = -3.4e38f;

    for (int j = tid; j < N; j += 4 * TPB) {
        float4 pa = p2[j];
        float4 pb = p2[j + TPB];
        float4 pc = p2[j + 2 * TPB];
        float4 pd = p2[j + 3 * TPB];
#pragma unroll
        for (int r = 0; r < RW; r++) {
            float a = fmaxf(hdot(xs[r], ys[r], zs[r], pa),
                            hdot(xs[r], ys[r], zs[r], pb));
            float b = fmaxf(hdot(xs[r], ys[r], zs[r], pc),
                            hdot(xs[r], ys[r], zs[r], pd));
            hm[r] = fmaxf(hm[r], fmaxf(a, b));
        }
    }
#pragma unroll
    for (int r = 0; r < RW; r++) {
#pragma unroll
        for (int ofs = 16; ofs > 0; ofs >>= 1)
            hm[r] = fmaxf(hm[r], __shfl_xor_sync(0xFFFFFFFFu, hm[r], ofs));
    }
    if (lane == 0) {
#pragma unroll
        for (int r = 0; r < RW; r++) s_hm[wrp][r] = hm[r];
    }
    __syncthreads();

    // Thresholds (redundant per thread; identical results).
    // Dense rows: gate off (+inf) here, handled by dense_kernel.
    float m[RW], hth[RW];
#pragma unroll
    for (int r = 0; r < RW; r++) {
        float h = fmaxf(s_hm[0][r], s_hm[1][r]);   // exact fp32 row max
        float mind2 = fmaf(-2.0f, h, s1[r]);
        float mm = FACT / fmaxf(mind2, EPS);
        m[r] = mm;
        if (mm < DENSE_TH) {
            hth[r] = __int_as_float(0x7f800000);    // +inf
        } else {
            float t = 0.5f * (s1[r] - FACT / (mm - CUTOFF));
            hth[r] = fminf(t, h);  // clamp: argmax qualifies bitwise in pass 2
        }
    }
    // Append dense rows to compact list (one thread per row)
    if (tid < RW) {
        int r = tid;
        g_rowm[row0 + r] = m[r];
        if (m[r] < DENSE_TH) {
            int e = atomicAdd(&g_dense_cnt, 1);
            g_dense_rows[e] = row0 + r;
        }
    }

    // ---- Pass 2: PER-ROW gate (tight); exp only where mass is non-negligible ----
    float sw[RW], ax[RW], ay[RW], az[RW];
#pragma unroll
    for (int r = 0; r < RW; r++) { sw[r] = 0.f; ax[r] = 0.f; ay[r] = 0.f; az[r] = 0.f; }

    for (int j = tid; j < N; j += 2 * TPB) {
        float4 pa = p2[j];
        float4 pb = p2[j + TPB];
        float ha[RW], hb[RW];
        float g = -3.4e38f;
#pragma unroll
        for (int r = 0; r < RW; r++) {
            ha[r] = hdot(xs[r], ys[r], zs[r], pa);   // identical chain to pass 1
            hb[r] = hdot(xs[r], ys[r], zs[r], pb);
            g = fmaxf(g, fmaxf(ha[r], hb[r]) - hth[r]);
        }
        if (g >= 0.0f) {   // rare: tight qualifier ball for sparse rows
#pragma unroll
            for (int r = 0; r < RW; r++) {
                if (ha[r] >= hth[r]) {
                    float d2 = fmaf(-2.0f, ha[r], s1[r]);
                    float w = __expf(FACT / fmaxf(d2, EPS) - m[r]);
                    sw[r] += w;
                    ax[r] = fmaf(w, pa.x, ax[r]);
                    ay[r] = fmaf(w, pa.y, ay[r]);
                    az[r] = fmaf(w, pa.z, az[r]);
                }
                if (hb[r] >= hth[r]) {
                    float d2 = fmaf(-2.0f, hb[r], s1[r]);
                    float w = __expf(FACT / fmaxf(d2, EPS) - m[r]);
                    sw[r] += w;
                    ax[r] = fmaf(w, pb.x, ax[r]);
                    ay[r] = fmaf(w, pb.y, ay[r]);
                    az[r] = fmaf(w, pb.z, az[r]);
                }
            }
        }
    }

#pragma unroll
    for (int r = 0; r < RW; r++) {
#pragma unroll
        for (int ofs = 16; ofs > 0; ofs >>= 1) {
            sw[r] += __shfl_xor_sync(0xFFFFFFFFu, sw[r], ofs);
            ax[r] += __shfl_xor_sync(0xFFFFFFFFu, ax[r], ofs);
            ay[r] += __shfl_xor_sync(0xFFFFFFFFu, ay[r], ofs);
            az[r] += __shfl_xor_sync(0xFFFFFFFFu, az[r], ofs);
        }
    }
    if (lane == 0) {
#pragma unroll
        for (int r = 0; r < RW; r++) {
            s_acc[wrp][r][0] = sw[r];
            s_acc[wrp][r][1] = ax[r];
            s_acc[wrp][r][2] = ay[r];
            s_acc[wrp][r][3] = az[r];
        }
    }
    __syncthreads();

    if (tid < RW) {
        int r = tid;
        if (m[r] >= DENSE_TH) {             // sparse rows finalized here
            int i = row0 + r;
            float swt = s_acc[0][r][0] + s_acc[1][r][0];
            float axt = s_acc[0][r][1] + s_acc[1][r][1];
            float ayt = s_acc[0][r][2] + s_acc[1][r][2];
            float azt = s_acc[0][r][3] + s_acc[1][r][3];
            float inv = 1.0f / swt;
            float px = axt * inv, py = ayt * inv, pz = azt * inv;
            out[i] = px;
            out[N + i] = py;
            out[2 * N + i] = pz;
            float dx = xs[r] - px + PD_EPS;
            float dy = ys[r] - py + PD_EPS;
            float dz = zs[r] - pz + PD_EPS;
            g_pd[i] = sqrtf(fmaf(dx, dx, fmaf(dy, dy, dz * dz)));
        }
    }
}

// ---- Dense rows via compact list, high occupancy; last CTA does the mean ----
__global__ __launch_bounds__(TPB_D)
void dense_kernel(const float* __restrict__ pc1, float* __restrict__ out,
                  int out_size) {
    __shared__ float s_red[8][4];
    __shared__ float s_mean[8];
    __shared__ int s_last;

    const int tid = threadIdx.x;
    const int lane = tid & 31;
    const int wrp = tid >> 5;
    const int cnt = g_dense_cnt;             // written by soft_knn_kernel
    const float4* __restrict__ p2 = g_p2;

    for (int e = blockIdx.x; e < cnt; e += GRID_D) {
        const int row = g_dense_rows[e];
        const float m = g_rowm[row];
        float x1 = pc1[row], y1 = pc1[N + row], z1 = pc1[2 * N + row];
        float s1 = fmaf(x1, x1, fmaf(y1, y1, z1 * z1));

        float sw = 0.f, ax = 0.f, ay = 0.f, az = 0.f;
        for (int j = tid; j < N; j += 4 * TPB_D) {   // unroll x4, MLP 4
            float4 ps[4] = {p2[j], p2[j + TPB_D], p2[j + 2 * TPB_D], p2[j + 3 * TPB_D]};
#pragma unroll
            for (int q = 0; q < 4; q++) {
                float h = hdot(x1, y1, z1, ps[q]);
                float d2 = fmaf(-2.0f, h, s1);
                float w = __expf(FACT / fmaxf(d2, EPS) - m);   // m exact: no overflow
                sw += w;
                ax = fmaf(w, ps[q].x, ax);
                ay = fmaf(w, ps[q].y, ay);
                az = fmaf(w, ps[q].z, az);
            }
        }
#pragma unroll
        for (int ofs = 16; ofs > 0; ofs >>= 1) {
            sw += __shfl_xor_sync(0xFFFFFFFFu, sw, ofs);
            ax += __shfl_xor_sync(0xFFFFFFFFu, ax, ofs);
            ay += __shfl_xor_sync(0xFFFFFFFFu, ay, ofs);
            az += __shfl_xor_sync(0xFFFFFFFFu, az, ofs);
        }
        if (lane == 0) {
            s_red[wrp][0] = sw;
            s_red[wrp][1] = ax;
            s_red[wrp][2] = ay;
            s_red[wrp][3] = az;
        }
        __syncthreads();
        if (tid == 0) {
            float swt = 0.f, axt = 0.f, ayt = 0.f, azt = 0.f;
#pragma unroll
            for (int w8 = 0; w8 < 8; w8++) {   // fixed order: deterministic
                swt += s_red[w8][0];
                axt += s_red[w8][1];
                ayt += s_red[w8][2];
                azt += s_red[w8][3];
            }
            float inv = 1.0f / swt;
            float px = axt * inv, py = ayt * inv, pz = azt * inv;
            out[row] = px;
            out[N + row] = py;
            out[2 * N + row] = pz;
            float dx = x1 - px + PD_EPS;
            float dy = y1 - py + PD_EPS;
            float dz = z1 - pz + PD_EPS;
            g_pd[row] = sqrtf(fmaf(dx, dx, fmaf(dy, dy, dz * dz)));
        }
        __syncthreads();
    }

    // Completion handshake (ALL CTAs, incl. ones with no list entries)
    __threadfence();
    if (tid == 0) s_last = (atomicAdd(&g_done, 1) == GRID_D - 1);
    __syncthreads();
    if (s_last) {
        __threadfence();   // acquire: order g_pd reads after the counter
        float acc = 0.f;
        for (int i = tid; i < N; i += TPB_D) acc += __ldcg(&g_pd[i]);
#pragma unroll
        for (int ofs = 16; ofs > 0; ofs >>= 1)
            acc += __shfl_xor_sync(0xFFFFFFFFu, acc, ofs);
        if (lane == 0) s_mean[wrp] = acc;
        __syncthreads();
        if (tid == 0 && out_size > 3 * N) {
            float t = 0.f;
#pragma unroll
            for (int w8 = 0; w8 < 8; w8++) t += s_mean[w8];
            out[3 * N] = t * (1.0f / N);
        }
    }
}

extern "C" void kernel_launch(void* const* d_in, const int* in_sizes, int n_in,
                              void* d_out, int out_size) {
    const float* pc1 = (const float*)d_in[0];
    const float* pc2 = (const float*)d_in[1];
    float* out = (float*)d_out;

    prep_kernel<<<(N + 255) / 256, 256>>>(pc2);
    soft_knn_kernel<<<GRID, TPB>>>(pc1, out);
    dense_kernel<<<GRID_D, TPB_D>>>(pc1, out, out_size);
}

// round 14
// speedup vs baseline: 1.5762x; 1.0373x over previous
#include <cuda_runtime.h>
#include <cuda_bf16.h>
#include <math.h>

#define N 8192
#define EPS 1e-5f
#define FACT 2.0f
#define PD_EPS 1e-6f
#define CUTOFF 25.0f
#define DENSE_TH 32.0f   // rows with m < 32 handled by dense_kernel

#define RW 4
#define TPB 64
#define GRID (N / RW)    // 2048 CTAs
#define GRID_D 1184      // dense kernel CTAs (8/SM at 256 thr)
#define TPB_D 256

__device__ float4 g_p2[N];        // packed {x, y, z, -0.5*|p|^2}
__device__ float g_rowm[N];       // softmax max arg per row (exact)
__device__ float g_pd[N];         // per-row pairwise distance
__device__ int g_dense_rows[N];   // compacted dense row indices
__device__ int g_dense_cnt;       // number of dense rows
__device__ int g_done;            // dense-kernel completion counter

// h = dot(p1, p2_j) - 0.5*|p2_j|^2  (argmax h == argmin d2; d2 = s1 - 2h)
__device__ __forceinline__ float hdot(float x, float y, float z, float4 p) {
    return fmaf(x, p.x, fmaf(y, p.y, fmaf(z, p.z, p.w)));
}

__global__ void prep_kernel(const float* __restrict__ pc2) {
    int j = blockIdx.x * blockDim.x + threadIdx.x;
    if (j == 0) { g_dense_cnt = 0; g_done = 0; }   // re-seed (graph-replay safe)
    if (j < N) {
        float x = pc2[j], y = pc2[N + j], z = pc2[2 * N + j];
        g_p2[j] = make_float4(x, y, z, -0.5f * fmaf(x, x, fmaf(y, y, z * z)));
    }
}

// ---- Fused: pass1 max -> classify -> pass2 gated acc (sparse rows only) ----
__global__ __launch_bounds__(TPB, 14)
void soft_knn_kernel(const float* __restrict__ pc1, float* __restrict__ out) {
    __shared__ float s_hm[2][RW];
    __shared__ float s_acc[2][RW][4];

    const int tid = threadIdx.x;
    const int lane = tid & 31;
    const int wrp = tid >> 5;
    const int row0 = blockIdx.x * RW;
    const float4* __restrict__ p2 = g_p2;

    float xs[RW], ys[RW], zs[RW], s1[RW];
#pragma unroll
    for (int r = 0; r < RW; r++) {
        int i = row0 + r;
        xs[r] = pc1[i];
        ys[r] = pc1[N + i];
        zs[r] = pc1[2 * N + i];
        s1[r] = fmaf(xs[r], xs[r], fmaf(ys[r], ys[r], zs[r] * zs[r]));
    }

    // ---- Pass 1: per-row hmax; 64 threads sweep j, unroll x4 ----
    float hm[RW];
#pragma unroll
    for (int r = 0; r < RW; r++) hm[r] = -3.4e38f;

    for (int j = tid; j < N; j += 4 * TPB) {
        float4 pa = p2[j];
        float4 pb = p2[j + TPB];
        float4 pc = p2[j + 2 * TPB];
        float4 pd = p2[j + 3 * TPB];
#pragma unroll
        for (int r = 0; r < RW; r++) {
            float a = fmaxf(hdot(xs[r], ys[r], zs[r], pa),
                            hdot(xs[r], ys[r], zs[r], pb));
            float b = fmaxf(hdot(xs[r], ys[r], zs[r], pc),
                            hdot(xs[r], ys[r], zs[r], pd));
            hm[r] = fmaxf(hm[r], fmaxf(a, b));
        }
    }
#pragma unroll
    for (int r = 0; r < RW; r++) {
#pragma unroll
        for (int ofs = 16; ofs > 0; ofs >>= 1)
            hm[r] = fmaxf(hm[r], __shfl_xor_sync(0xFFFFFFFFu, hm[r], ofs));
    }
    if (lane == 0) {
#pragma unroll
        for (int r = 0; r < RW; r++) s_hm[wrp][r] = hm[r];
    }
    __syncthreads();

    // Thresholds (redundant per thread; identical results).
    // Dense rows: gate off (+inf) here, handled by dense_kernel.
    float m[RW], hth[RW];
#pragma unroll
    for (int r = 0; r < RW; r++) {
        float h = fmaxf(s_hm[0][r], s_hm[1][r]);   // exact fp32 row max
        float mind2 = fmaf(-2.0f, h, s1[r]);
        float mm = FACT / fmaxf(mind2, EPS);
        m[r] = mm;
        if (mm < DENSE_TH) {
            hth[r] = __int_as_float(0x7f800000);    // +inf
        } else {
            float t = 0.5f * (s1[r] - FACT / (mm - CUTOFF));
            hth[r] = fminf(t, h);  // clamp: argmax qualifies bitwise in pass 2
        }
    }
    // Append dense rows to compact list (one thread per row)
    if (tid < RW) {
        int r = tid;
        g_rowm[row0 + r] = m[r];
        if (m[r] < DENSE_TH) {
            int e = atomicAdd(&g_dense_cnt, 1);
            g_dense_rows[e] = row0 + r;
        }
    }

    // ---- Pass 2: loads front-batched x4 (MLP 4), two per-row gates per block ----
    float sw[RW], ax[RW], ay[RW], az[RW];
#pragma unroll
    for (int r = 0; r < RW; r++) { sw[r] = 0.f; ax[r] = 0.f; ay[r] = 0.f; az[r] = 0.f; }

    for (int j = tid; j < N; j += 4 * TPB) {
        float4 pa = p2[j];
        float4 pb = p2[j + TPB];
        float4 pc = p2[j + 2 * TPB];
        float4 pd = p2[j + 3 * TPB];

        // group 1: pa, pb
        {
            float ha[RW], hb[RW];
            float g = -3.4e38f;
#pragma unroll
            for (int r = 0; r < RW; r++) {
                ha[r] = hdot(xs[r], ys[r], zs[r], pa);   // identical chain to pass 1
                hb[r] = hdot(xs[r], ys[r], zs[r], pb);
                g = fmaxf(g, fmaxf(ha[r], hb[r]) - hth[r]);
            }
            if (g >= 0.0f) {
#pragma unroll
                for (int r = 0; r < RW; r++) {
                    if (ha[r] >= hth[r]) {
                        float d2 = fmaf(-2.0f, ha[r], s1[r]);
                        float w = __expf(FACT / fmaxf(d2, EPS) - m[r]);
                        sw[r] += w;
                        ax[r] = fmaf(w, pa.x, ax[r]);
                        ay[r] = fmaf(w, pa.y, ay[r]);
                        az[r] = fmaf(w, pa.z, az[r]);
                    }
                    if (hb[r] >= hth[r]) {
                        float d2 = fmaf(-2.0f, hb[r], s1[r]);
                        float w = __expf(FACT / fmaxf(d2, EPS) - m[r]);
                        sw[r] += w;
                        ax[r] = fmaf(w, pb.x, ax[r]);
                        ay[r] = fmaf(w, pb.y, ay[r]);
                        az[r] = fmaf(w, pb.z, az[r]);
                    }
                }
            }
        }
        // group 2: pc, pd
        {
            float ha[RW], hb[RW];
            float g = -3.4e38f;
#pragma unroll
            for (int r = 0; r < RW; r++) {
                ha[r] = hdot(xs[r], ys[r], zs[r], pc);
                hb[r] = hdot(xs[r], ys[r], zs[r], pd);
                g = fmaxf(g, fmaxf(ha[r], hb[r]) - hth[r]);
            }
            if (g >= 0.0f) {
#pragma unroll
                for (int r = 0; r < RW; r++) {
                    if (ha[r] >= hth[r]) {
                        float d2 = fmaf(-2.0f, ha[r], s1[r]);
                        float w = __expf(FACT / fmaxf(d2, EPS) - m[r]);
                        sw[r] += w;
                        ax[r] = fmaf(w, pc.x, ax[r]);
                        ay[r] = fmaf(w, pc.y, ay[r]);
                        az[r] = fmaf(w, pc.z, az[r]);
                    }
                    if (hb[r] >= hth[r]) {
                        float d2 = fmaf(-2.0f, hb[r], s1[r]);
                        float w = __expf(FACT / fmaxf(d2, EPS) - m[r]);
                        sw[r] += w;
                        ax[r] = fmaf(w, pd.x, ax[r]);
                        ay[r] = fmaf(w, pd.y, ay[r]);
                        az[r] = fmaf(w, pd.z, az[r]);
                    }
                }
            }
        }
    }

#pragma unroll
    for (int r = 0; r < RW; r++) {
#pragma unroll
        for (int ofs = 16; ofs > 0; ofs >>= 1) {
            sw[r] += __shfl_xor_sync(0xFFFFFFFFu, sw[r], ofs);
            ax[r] += __shfl_xor_sync(0xFFFFFFFFu, ax[r], ofs);
            ay[r] += __shfl_xor_sync(0xFFFFFFFFu, ay[r], ofs);
            az[r] += __shfl_xor_sync(0xFFFFFFFFu, az[r], ofs);
        }
    }
    if (lane == 0) {
#pragma unroll
        for (int r = 0; r < RW; r++) {
            s_acc[wrp][r][0] = sw[r];
            s_acc[wrp][r][1] = ax[r];
            s_acc[wrp][r][2] = ay[r];
            s_acc[wrp][r][3] = az[r];
        }
    }
    __syncthreads();

    if (tid < RW) {
        int r = tid;
        if (m[r] >= DENSE_TH) {             // sparse rows finalized here
            int i = row0 + r;
            float swt = s_acc[0][r][0] + s_acc[1][r][0];
            float axt = s_acc[0][r][1] + s_acc[1][r][1];
            float ayt = s_acc[0][r][2] + s_acc[1][r][2];
            float azt = s_acc[0][r][3] + s_acc[1][r][3];
            float inv = 1.0f / swt;
            float px = axt * inv, py = ayt * inv, pz = azt * inv;
            out[i] = px;
            out[N + i] = py;
            out[2 * N + i] = pz;
            float dx = xs[r] - px + PD_EPS;
            float dy = ys[r] - py + PD_EPS;
            float dz = zs[r] - pz + PD_EPS;
            g_pd[i] = sqrtf(fmaf(dx, dx, fmaf(dy, dy, dz * dz)));
        }
    }
}

// ---- Dense rows via compact list, high occupancy; last CTA does the mean ----
__global__ __launch_bounds__(TPB_D)
void dense_kernel(const float* __restrict__ pc1, float* __restrict__ out,
                  int out_size) {
    __shared__ float s_red[8][4];
    __shared__ float s_mean[8];
    __shared__ int s_last;

    const int tid = threadIdx.x;
    const int lane = tid & 31;
    const int wrp = tid >> 5;
    const int cnt = g_dense_cnt;             // written by soft_knn_kernel
    const float4* __restrict__ p2 = g_p2;

    for (int e = blockIdx.x; e < cnt; e += GRID_D) {
        const int row = g_dense_rows[e];
        const float m = g_rowm[row];
        float x1 = pc1[row], y1 = pc1[N + row], z1 = pc1[2 * N + row];
        float s1 = fmaf(x1, x1, fmaf(y1, y1, z1 * z1));

        float sw = 0.f, ax = 0.f, ay = 0.f, az = 0.f;
        for (int j = tid; j < N; j += 4 * TPB_D) {   // unroll x4, MLP 4
            float4 ps[4] = {p2[j], p2[j + TPB_D], p2[j + 2 * TPB_D], p2[j + 3 * TPB_D]};
#pragma unroll
            for (int q = 0; q < 4; q++) {
                float h = hdot(x1, y1, z1, ps[q]);
                float d2 = fmaf(-2.0f, h, s1);
                float w = __expf(FACT / fmaxf(d2, EPS) - m);   // m exact: no overflow
                sw += w;
                ax = fmaf(w, ps[q].x, ax);
                ay = fmaf(w, ps[q].y, ay);
                az = fmaf(w, ps[q].z, az);
            }
        }
#pragma unroll
        for (int ofs = 16; ofs > 0; ofs >>= 1) {
            sw += __shfl_xor_sync(0xFFFFFFFFu, sw, ofs);
            ax += __shfl_xor_sync(0xFFFFFFFFu, ax, ofs);
            ay += __shfl_xor_sync(0xFFFFFFFFu, ay, ofs);
            az += __shfl_xor_sync(0xFFFFFFFFu, az, ofs);
        }
        if (lane == 0) {
            s_red[wrp][0] = sw;
            s_red[wrp][1] = ax;
            s_red[wrp][2] = ay;
            s_red[wrp][3] = az;
        }
        __syncthreads();
        if (tid == 0) {
            float swt = 0.f, axt = 0.f, ayt = 0.f, azt = 0.f;
#pragma unroll
            for (int w8 = 0; w8 < 8; w8++) {   // fixed order: deterministic
                swt += s_red[w8][0];
                axt += s_red[w8][1];
                ayt += s_red[w8][2];
                azt += s_red[w8][3];
            }
            float inv = 1.0f / swt;
            float px = axt * inv, py = ayt * inv, pz = azt * inv;
            out[row] = px;
            out[N + row] = py;
            out[2 * N + row] = pz;
            float dx = x1 - px + PD_EPS;
            float dy = y1 - py + PD_EPS;
            float dz = z1 - pz + PD_EPS;
            g_pd[row] = sqrtf(fmaf(dx, dx, fmaf(dy, dy, dz * dz)));
        }
        __syncthreads();
    }

    // Completion handshake (ALL CTAs, incl. ones with no list entries)
    __threadfence();
    if (tid == 0) s_last = (atomicAdd(&g_done, 1) == GRID_D - 1);
    __syncthreads();
    if (s_last) {
        __threadfence();   // acquire: order g_pd reads after the counter
        float acc = 0.f;
        for (int i = tid; i < N; i += TPB_D) acc += __ldcg(&g_pd[i]);
#pragma unroll
        for (int ofs = 16; ofs > 0; ofs >>= 1)
            acc += __shfl_xor_sync(0xFFFFFFFFu, acc, ofs);
        if (lane == 0) s_mean[wrp] = acc;
        __syncthreads();
        if (tid == 0 && out_size > 3 * N) {
            float t = 0.f;
#pragma unroll
            for (int w8 = 0; w8 < 8; w8++) t += s_mean[w8];
            out[3 * N] = t * (1.0f / N);
        }
    }
}

extern "C" void kernel_launch(void* const* d_in, const int* in_sizes, int n_in,
                              void* d_out, int out_size) {
    const float* pc1 = (const float*)d_in[0];
    const float* pc2 = (const float*)d_in[1];
    float* out = (float*)d_out;

    prep_kernel<<<(N + 255) / 256, 256>>>(pc2);
    soft_knn_kernel<<<GRID, TPB>>>(pc1, out);
    dense_kernel<<<GRID_D, TPB_D>>>(pc1, out, out_size);
}